// round 9
// baseline (speedup 1.0000x reference)
#include <cuda_runtime.h>
#include <cuda_bf16.h>

#define NPRI    8732
#define NCLS    21
#define NBATCH  8
#define NLANES  (NBATCH * NCLS)   // 168
#define TOPK    200
#define MCAND   600
#define NGMAX   19                // ceil(MCAND/32)
#define MPITCH  601               // odd pitch -> conflict-free lane*MPITCH
#define CAP     1024
#define CONF_TH 0.95f
#define NMS_TH  0.45f
#define NTHREADS 512
#define NWARPS  16

struct __align__(16) Smem {
    unsigned long long key[CAP];        // sorted candidate keys
    float4             box[MCAND];      // sorted-order boxes
    float              area[MCAND];
    float4             wbox[MCAND];     // compacted well-formed boxes
    float              warea[MCAND];
    unsigned           wmask[NGMAX * MPITCH]; // IoU bits on compact indices
    short              cidx[MCAND];     // orig -> compact (-1 = degenerate)
    unsigned           wfball[NGMAX];   // wf ballots per 32-chunk
    unsigned           flagb[NGMAX];    // keep-flag ballots per 32-chunk
    int                wfoff[NGMAX + 1];
    int                ctoff[NGMAX + 1];
    unsigned           kwbits[NGMAX];   // compact keep bits per 32-chunk
    int                count, fp, nwf, ntot;
};

static __device__ __forceinline__ unsigned long long shfl_xor_u64(unsigned long long v, int m) {
    unsigned lo = __shfl_xor_sync(0xFFFFFFFFu, (unsigned)v, m);
    unsigned hi = __shfl_xor_sync(0xFFFFFFFFu, (unsigned)(v >> 32), m);
    return ((unsigned long long)hi << 32) | lo;
}

__global__ void __launch_bounds__(NTHREADS, 2)
detect_kernel(const float* __restrict__ loc,
              const float* __restrict__ conf,
              float* __restrict__ out)
{
    extern __shared__ unsigned char raw[];
    Smem& S = *reinterpret_cast<Smem*>(raw);

    const int lane_id = blockIdx.x;
    const int b = lane_id / NCLS, c = lane_id % NCLS;
    float* outp = out + (size_t)lane_id * TOPK * 5;
    const int tid = threadIdx.x, lane = tid & 31, warp = tid >> 5;
    const unsigned lanem_lt = (1u << lane) - 1u;

    if (c == 0) {
        for (int i = tid; i < TOPK * 5; i += NTHREADS) outp[i] = 0.0f;
        return;
    }
    if (tid == 0) { S.count = 0; S.fp = 0x7FFFFFFF; }
    __syncthreads();

    // ================= Phase A: collect passers (9-deep preload x2) =================
    const float* confc = conf + (size_t)b * NPRI * NCLS + c;
    #pragma unroll
    for (int half = 0; half < 2; ++half) {
        float sv[9];
        #pragma unroll
        for (int t = 0; t < 9; ++t) {
            int p = tid + (half * 9 + t) * NTHREADS;
            sv[t] = (p < NPRI) ? __ldg(&confc[(size_t)p * NCLS]) : 0.0f;
        }
        #pragma unroll
        for (int t = 0; t < 9; ++t) {
            int p = tid + (half * 9 + t) * NTHREADS;
            bool pass = sv[t] > CONF_TH;
            unsigned m = __ballot_sync(0xFFFFFFFFu, pass);
            if (m) {
                int leader = __ffs(m) - 1, bp = 0;
                if (lane == leader) {
                    bp = atomicAdd(&S.count, __popc(m));
                    atomicMin(&S.fp, p);
                }
                bp = __shfl_sync(0xFFFFFFFFu, bp, leader);
                if (pass) {
                    int pos = bp + __popc(m & lanem_lt);
                    if (pos < CAP)
                        S.key[pos] = ((unsigned long long)__float_as_uint(sv[t]) << 32)
                                   | (unsigned)(0xFFFFFFFFu - (unsigned)p);
                }
            }
        }
    }
    __syncthreads();
    const int count = min(S.count, CAP);
    if (count == 0) {
        for (int i = tid; i < TOPK * 5; i += NTHREADS) outp[i] = 0.0f;
        return;
    }

    // ================= Phase B: descending bitonic sort =================
    if (count <= 512) {
        unsigned long long v = (tid < count) ? S.key[tid] : 0ull;
        #pragma unroll
        for (int k = 2; k <= 32; k <<= 1) {
            #pragma unroll
            for (int j = k >> 1; j; j >>= 1) {
                unsigned long long o = shfl_xor_u64(v, j);
                bool takeMax = (((tid & k) == 0) == ((tid & j) == 0));
                bool gt = v > o;
                v = (takeMax == gt) ? v : o;
            }
        }
        S.key[tid] = v;
        #pragma unroll
        for (int k = 64; k <= 512; k <<= 1) {
            for (int j = k >> 1; j >= 32; j >>= 1) {
                __syncthreads();
                if ((tid & j) == 0) {
                    int l = tid ^ j;
                    unsigned long long a = S.key[tid], bb = S.key[l];
                    if (((tid & k) == 0) ? (a < bb) : (a > bb)) { S.key[tid] = bb; S.key[l] = a; }
                }
            }
            __syncthreads();
            v = S.key[tid];
            const bool up = ((tid & k) == 0);
            #pragma unroll
            for (int j = 16; j; j >>= 1) {
                unsigned long long o = shfl_xor_u64(v, j);
                bool takeMax = (up == ((tid & j) == 0));
                bool gt = v > o;
                v = (takeMax == gt) ? v : o;
            }
            S.key[tid] = v;
        }
        __syncthreads();
    } else {
        const int n2 = 1 << (32 - __clz(count - 1));
        for (int i = count + tid; i < n2; i += NTHREADS) S.key[i] = 0ull;
        for (int k = 2; k <= n2; k <<= 1) {
            for (int j = k >> 1; j > 0; j >>= 1) {
                __syncthreads();
                for (int i = tid; i < n2; i += NTHREADS) {
                    int l = i ^ j;
                    if (l > i) {
                        unsigned long long a = S.key[i], bb = S.key[l];
                        if (((i & k) == 0) ? (a < bb) : (a > bb)) { S.key[i] = bb; S.key[l] = a; }
                    }
                }
            }
        }
        __syncthreads();
    }

    // ================= Phase C: gather boxes =================
    const int M = min(count, MCAND);
    const int ngroups = (M + 31) >> 5;
    for (int t = tid; t < M; t += NTHREADS) {
        int p = (int)(0xFFFFFFFFu - (unsigned)(S.key[t] & 0xFFFFFFFFu));
        float4 L = __ldg((const float4*)(loc + ((size_t)b * NPRI + p) * 4));
        S.box[t]  = L;
        S.area[t] = (L.z - L.x) * (L.w - L.y);
    }
    __syncthreads();

    // ====== Phase C2: order-preserving compaction of well-formed boxes ======
    // Degenerate boxes (w<=0 or h<=0) have clipped inter == 0 with EVERY box,
    // so iou in {0,-0,NaN}: never > 0.45. They never suppress / are never
    // suppressed -> NMS graph lives entirely on the well-formed subset.
    for (int cs = warp; cs < ngroups; cs += NWARPS) {
        int t = cs * 32 + lane;
        bool wf = false;
        if (t < M) { float4 B = S.box[t]; wf = (B.z > B.x) && (B.w > B.y); }
        unsigned m = __ballot_sync(0xFFFFFFFFu, wf);
        if (lane == 0) { S.wfball[cs] = m; S.wfoff[cs] = __popc(m); }
    }
    __syncthreads();
    if (tid == 0) {
        int run = 0;
        for (int cs = 0; cs < ngroups; ++cs) { int cc = S.wfoff[cs]; S.wfoff[cs] = run; run += cc; }
        S.nwf = run;
    }
    __syncthreads();
    const int nwf = S.nwf;
    for (int cs = warp; cs < ngroups; cs += NWARPS) {
        int t = cs * 32 + lane;
        if (t < M) {
            unsigned m = S.wfball[cs];
            bool wf = (m >> lane) & 1u;
            int pos = S.wfoff[cs] + __popc(m & lanem_lt);
            S.cidx[t] = wf ? (short)pos : (short)-1;
            if (wf) { S.wbox[pos] = S.box[t]; S.warea[pos] = S.area[t]; }
        }
    }
    __syncthreads();

    const int ngw = (nwf + 31) >> 5;

    // ================= Phase D: IoU mask on compact set (tiny triangle) =================
    {
        int tcnt = 0;
        for (int w = 0; w < ngw; ++w) {
            const int j0 = w * 32;
            const int jmax = min(32, nwf - j0);
            for (int g = 0; g <= w; ++g, ++tcnt) {
                if ((tcnt & (NWARPS - 1)) != warp) continue;
                const int i = g * 32 + lane;
                const bool rv = i < nwf;
                float4 bi = rv ? S.wbox[i] : make_float4(0, 0, 0, 0);
                float  ai = rv ? S.warea[i] : 0.0f;
                unsigned bits = 0, uncb = 0;
                #pragma unroll 8
                for (int t2 = 0; t2 < jmax; ++t2) {
                    float4 bj = S.wbox[j0 + t2];
                    float  aj = S.warea[j0 + t2];
                    float inter = fmaxf(fminf(bi.z, bj.z) - fmaxf(bi.x, bj.x), 0.0f)
                                * fmaxf(fminf(bi.w, bj.w) - fmaxf(bi.y, bj.y), 0.0f);
                    float un = ai + aj - inter;
                    // division-free surrogate for fdiv_rn(inter,un) > 0.45f
                    float d  = fmaf(-NMS_TH, un, inter);
                    float mg = 2e-6f * (fabsf(inter) + fabsf(un));
                    bool sup = (un > 0.0f) ? (d > mg) : (d < -mg);
                    bool unc = !(fabsf(d) > mg) || (un == 0.0f);
                    if (sup) bits |= 1u << t2;
                    if (unc) uncb |= 1u << t2;
                }
                if (uncb) {                        // rare exact fixup
                    do {
                        int t2 = __ffs(uncb) - 1; uncb &= uncb - 1;
                        float4 bj = S.wbox[j0 + t2];
                        float  aj = S.warea[j0 + t2];
                        float inter = fmaxf(fminf(bi.z, bj.z) - fmaxf(bi.x, bj.x), 0.0f)
                                    * fmaxf(fminf(bi.w, bj.w) - fmaxf(bi.y, bj.y), 0.0f);
                        float un = ai + aj - inter;
                        if (__fdiv_rn(inter, un) > NMS_TH) bits |= 1u << t2;
                        else bits &= ~(1u << t2);
                    } while (uncb);
                }
                if (g == w) bits &= (0xFFFFFFFEu << lane);    // keep only j > i
                if (rv) S.wmask[w * MPITCH + i] = bits;
            }
        }
    }
    __syncthreads();

    // ================= Phase E: compact greedy sweep (warp 0) =================
    if (warp == 0 && nwf > 0) {
        unsigned acc = 0;
        for (int w = 0; w < ngw; ++w) {
            unsigned cur = __shfl_sync(0xFFFFFFFFu, acc, w);
            unsigned chunkkeep = 0;
            for (int sub = 0; sub < 4; ++sub) {
                const int ibase = w * 32 + sub * 8;
                if (ibase >= nwf) break;
                const int nv = min(8, nwf - ibase);
                const unsigned validm = (nv == 8) ? 0xFFu : ((1u << nv) - 1u);
                unsigned selfm[8], rowm[8], selfor = 0;
                #pragma unroll
                for (int t = 0; t < 8; ++t) {
                    bool vld = t < nv;
                    int i = ibase + t;
                    selfm[t] = vld ? S.wmask[w * MPITCH + i] : 0u;   // broadcast
                    rowm[t]  = (vld && lane >= w && lane < ngw)
                             ? S.wmask[lane * MPITCH + i] : 0u;
                    selfor |= selfm[t];
                }
                unsigned keepb;
                if (selfor == 0) {
                    keepb = validm & ~((cur >> (sub * 8)) & 0xFFu);
                    #pragma unroll
                    for (int t = 0; t < 8; ++t)
                        acc |= rowm[t] & (unsigned)(-(int)((keepb >> t) & 1u));
                } else {
                    keepb = 0;
                    #pragma unroll
                    for (int t = 0; t < 8; ++t) {
                        int kbit = sub * 8 + t;
                        if (((validm >> t) & 1u) && !((cur >> kbit) & 1u)) {
                            keepb |= 1u << t;
                            cur |= selfm[t];
                            acc |= rowm[t];
                        }
                    }
                }
                chunkkeep |= keepb << (sub * 8);
            }
            if (lane == 0) S.kwbits[w] = chunkkeep;
        }
    }
    __syncthreads();

    // ================= Phase F: flag scan + scatter output =================
    for (int cs = warp; cs < ngroups; cs += NWARPS) {
        int t = cs * 32 + lane;
        bool flag = false;
        if (t < M) {
            int ci = S.cidx[t];
            flag = (ci < 0) ? true : (((S.kwbits[ci >> 5] >> (ci & 31)) & 1u) != 0);
        }
        unsigned fb = __ballot_sync(0xFFFFFFFFu, flag);
        if (lane == 0) { S.flagb[cs] = fb; S.ctoff[cs] = __popc(fb); }
    }
    __syncthreads();
    if (tid == 0) {
        int run = 0;
        for (int cs = 0; cs < ngroups; ++cs) { int cc = S.ctoff[cs]; S.ctoff[cs] = run; run += cc; }
        S.ntot = run;
    }
    __syncthreads();
    const int n = min(S.ntot, TOPK);
    const int fp = S.fp;

    for (int cs = warp; cs < ngroups; cs += NWARPS) {
        int t = cs * 32 + lane;
        unsigned fb = S.flagb[cs];
        bool flag = ((fb >> lane) & 1u) && (t < M);
        int rank = S.ctoff[cs] + __popc(fb & lanem_lt);
        if (flag && rank < TOPK) {
            float sc = __uint_as_float((unsigned)(S.key[t] >> 32));
            float4 bb = S.box[t];
            float* o = outp + rank * 5;
            o[0] = sc; o[1] = bb.x; o[2] = bb.y; o[3] = bb.z; o[4] = bb.w;
        }
    }
    {
        float4 fb4 = __ldg((const float4*)(loc + ((size_t)b * NPRI + fp) * 4));
        for (int r = n + tid; r < TOPK; r += NTHREADS) {
            float* o = outp + r * 5;
            o[0] = 0.0f; o[1] = fb4.x; o[2] = fb4.y; o[3] = fb4.z; o[4] = fb4.w;
        }
    }
}

extern "C" void kernel_launch(void* const* d_in, const int* in_sizes, int n_in,
                              void* d_out, int out_size)
{
    const float* loc  = (const float*)d_in[0];   // [8, 8732, 4]
    const float* conf = (const float*)d_in[1];   // [8, 8732, 21]
    float* out = (float*)d_out;                  // [8, 21, 200, 5]

    static int configured = 0;
    if (!configured) {
        cudaFuncSetAttribute(detect_kernel,
                             cudaFuncAttributeMaxDynamicSharedMemorySize,
                             (int)sizeof(Smem));
        // Force max smem carveout so TWO 79KB blocks co-reside per SM:
        // kills the serialized second wave on the 20 tail SMs (168 vs 148).
        cudaFuncSetAttribute(detect_kernel,
                             cudaFuncAttributePreferredSharedMemoryCarveout,
                             100);
        configured = 1;
    }
    detect_kernel<<<NLANES, NTHREADS, sizeof(Smem)>>>(loc, conf, out);
}

// round 10
// speedup vs baseline: 1.1615x; 1.1615x over previous
#include <cuda_runtime.h>
#include <cuda_bf16.h>

#define NPRI    8732
#define NCLS    21
#define NBATCH  8
#define NLANES  (NBATCH * NCLS)   // 168
#define PPITCH  8736              // NPRI rounded to 32
#define TOPK    200
#define MCAND   600
#define NGMAX   19                // ceil(MCAND/32)
#define MPITCH  601               // odd pitch -> conflict-free lane*MPITCH
#define CAP     1024
#define CONF_TH 0.95f
#define NMS_TH  0.45f
#define NTHREADS 512
#define NWARPS  16

// transposed confidences: confT[b*NCLS + c][p] (coalesced per-lane reads)
__device__ float g_confT[NLANES][PPITCH];

struct __align__(16) Smem {
    unsigned long long key[CAP];
    float4             box[MCAND];
    float              area[MCAND];
    float4             wbox[MCAND];
    float              warea[MCAND];
    unsigned           wmask[NGMAX * MPITCH];
    short              cidx[MCAND];
    unsigned           wfball[NGMAX];
    unsigned           flagb[NGMAX];
    int                wfoff[NGMAX + 1];
    int                ctoff[NGMAX + 1];
    unsigned           kwbits[NGMAX];
    int                count, fp, nwf, ntot;
};

static __device__ __forceinline__ unsigned long long shfl_xor_u64(unsigned long long v, int m) {
    unsigned lo = __shfl_xor_sync(0xFFFFFFFFu, (unsigned)v, m);
    unsigned hi = __shfl_xor_sync(0xFFFFFFFFu, (unsigned)(v >> 32), m);
    return ((unsigned long long)hi << 32) | lo;
}

// ============ K0: tiled transpose conf[B,P,C] -> confT[B*C][P] ============
// Block = 672 threads = 32 priors x 21 classes. Reads coalesced (2688B run),
// smem stride-21 (coprime with 32 banks -> conflict-free), writes 128B/warp.
__global__ void __launch_bounds__(672)
k0_transpose(const float* __restrict__ conf)
{
    __shared__ float s[672];
    const int tile = blockIdx.x;           // 0 .. 8*273-1
    const int bb = tile / 273;
    const int p0 = (tile - bb * 273) * 32;
    const int tid = threadIdx.x;
    const int nv = min(32, NPRI - p0) * NCLS;    // valid elements this tile
    if (tid < nv)
        s[tid] = __ldg(conf + ((size_t)bb * NPRI + p0) * NCLS + tid);
    __syncthreads();
    const int c = tid / 32, pl = tid % 32;
    if (p0 + pl < NPRI)
        g_confT[bb * NCLS + c][p0 + pl] = s[pl * NCLS + c];
}

// ============ K1: detect (identical pipeline to R8, coalesced Phase A) ============
__global__ void __launch_bounds__(NTHREADS)
detect_kernel(const float* __restrict__ loc, float* __restrict__ out)
{
    extern __shared__ unsigned char raw[];
    Smem& S = *reinterpret_cast<Smem*>(raw);

    const int lane_id = blockIdx.x;
    const int b = lane_id / NCLS, c = lane_id % NCLS;
    float* outp = out + (size_t)lane_id * TOPK * 5;
    const int tid = threadIdx.x, lane = tid & 31, warp = tid >> 5;
    const unsigned lanem_lt = (1u << lane) - 1u;

    if (c == 0) {
        for (int i = tid; i < TOPK * 5; i += NTHREADS) outp[i] = 0.0f;
        return;
    }
    if (tid == 0) { S.count = 0; S.fp = 0x7FFFFFFF; }
    __syncthreads();

    // ---- Phase A: collect passers from transposed (coalesced) layout ----
    const float* confc = g_confT[lane_id];
    #pragma unroll
    for (int half = 0; half < 2; ++half) {
        float sv[9];
        #pragma unroll
        for (int t = 0; t < 9; ++t) {
            int p = tid + (half * 9 + t) * NTHREADS;
            sv[t] = (p < NPRI) ? confc[p] : 0.0f;
        }
        #pragma unroll
        for (int t = 0; t < 9; ++t) {
            int p = tid + (half * 9 + t) * NTHREADS;
            bool pass = sv[t] > CONF_TH;
            unsigned m = __ballot_sync(0xFFFFFFFFu, pass);
            if (m) {
                int leader = __ffs(m) - 1, bp = 0;
                if (lane == leader) {
                    bp = atomicAdd(&S.count, __popc(m));
                    atomicMin(&S.fp, p);
                }
                bp = __shfl_sync(0xFFFFFFFFu, bp, leader);
                if (pass) {
                    int pos = bp + __popc(m & lanem_lt);
                    if (pos < CAP)
                        S.key[pos] = ((unsigned long long)__float_as_uint(sv[t]) << 32)
                                   | (unsigned)(0xFFFFFFFFu - (unsigned)p);
                }
            }
        }
    }
    __syncthreads();
    const int count = min(S.count, CAP);
    if (count == 0) {
        for (int i = tid; i < TOPK * 5; i += NTHREADS) outp[i] = 0.0f;
        return;
    }

    // ---- Phase B: descending bitonic sort ----
    if (count <= 512) {
        unsigned long long v = (tid < count) ? S.key[tid] : 0ull;
        #pragma unroll
        for (int k = 2; k <= 32; k <<= 1) {
            #pragma unroll
            for (int j = k >> 1; j; j >>= 1) {
                unsigned long long o = shfl_xor_u64(v, j);
                bool takeMax = (((tid & k) == 0) == ((tid & j) == 0));
                bool gt = v > o;
                v = (takeMax == gt) ? v : o;
            }
        }
        S.key[tid] = v;
        #pragma unroll
        for (int k = 64; k <= 512; k <<= 1) {
            for (int j = k >> 1; j >= 32; j >>= 1) {
                __syncthreads();
                if ((tid & j) == 0) {
                    int l = tid ^ j;
                    unsigned long long a = S.key[tid], bb = S.key[l];
                    if (((tid & k) == 0) ? (a < bb) : (a > bb)) { S.key[tid] = bb; S.key[l] = a; }
                }
            }
            __syncthreads();
            v = S.key[tid];
            const bool up = ((tid & k) == 0);
            #pragma unroll
            for (int j = 16; j; j >>= 1) {
                unsigned long long o = shfl_xor_u64(v, j);
                bool takeMax = (up == ((tid & j) == 0));
                bool gt = v > o;
                v = (takeMax == gt) ? v : o;
            }
            S.key[tid] = v;
        }
        __syncthreads();
    } else {
        const int n2 = 1 << (32 - __clz(count - 1));
        for (int i = count + tid; i < n2; i += NTHREADS) S.key[i] = 0ull;
        for (int k = 2; k <= n2; k <<= 1) {
            for (int j = k >> 1; j > 0; j >>= 1) {
                __syncthreads();
                for (int i = tid; i < n2; i += NTHREADS) {
                    int l = i ^ j;
                    if (l > i) {
                        unsigned long long a = S.key[i], bb = S.key[l];
                        if (((i & k) == 0) ? (a < bb) : (a > bb)) { S.key[i] = bb; S.key[l] = a; }
                    }
                }
            }
        }
        __syncthreads();
    }

    // ---- Phase C: gather boxes ----
    const int M = min(count, MCAND);
    const int ngroups = (M + 31) >> 5;
    for (int t = tid; t < M; t += NTHREADS) {
        int p = (int)(0xFFFFFFFFu - (unsigned)(S.key[t] & 0xFFFFFFFFu));
        float4 L = __ldg((const float4*)(loc + ((size_t)b * NPRI + p) * 4));
        S.box[t]  = L;
        S.area[t] = (L.z - L.x) * (L.w - L.y);
    }
    __syncthreads();

    // ---- Phase C2: compaction of well-formed boxes (degenerates never interact) ----
    for (int cs = warp; cs < ngroups; cs += NWARPS) {
        int t = cs * 32 + lane;
        bool wf = false;
        if (t < M) { float4 B = S.box[t]; wf = (B.z > B.x) && (B.w > B.y); }
        unsigned m = __ballot_sync(0xFFFFFFFFu, wf);
        if (lane == 0) { S.wfball[cs] = m; S.wfoff[cs] = __popc(m); }
    }
    __syncthreads();
    if (tid == 0) {
        int run = 0;
        for (int cs = 0; cs < ngroups; ++cs) { int cc = S.wfoff[cs]; S.wfoff[cs] = run; run += cc; }
        S.nwf = run;
    }
    __syncthreads();
    const int nwf = S.nwf;
    for (int cs = warp; cs < ngroups; cs += NWARPS) {
        int t = cs * 32 + lane;
        if (t < M) {
            unsigned m = S.wfball[cs];
            bool wf = (m >> lane) & 1u;
            int pos = S.wfoff[cs] + __popc(m & lanem_lt);
            S.cidx[t] = wf ? (short)pos : (short)-1;
            if (wf) { S.wbox[pos] = S.box[t]; S.warea[pos] = S.area[t]; }
        }
    }
    __syncthreads();

    const int ngw = (nwf + 31) >> 5;

    // ---- Phase D: IoU mask on compact set ----
    {
        int tcnt = 0;
        for (int w = 0; w < ngw; ++w) {
            const int j0 = w * 32;
            const int jmax = min(32, nwf - j0);
            for (int g = 0; g <= w; ++g, ++tcnt) {
                if ((tcnt & (NWARPS - 1)) != warp) continue;
                const int i = g * 32 + lane;
                const bool rv = i < nwf;
                float4 bi = rv ? S.wbox[i] : make_float4(0, 0, 0, 0);
                float  ai = rv ? S.warea[i] : 0.0f;
                unsigned bits = 0, uncb = 0;
                #pragma unroll 8
                for (int t2 = 0; t2 < jmax; ++t2) {
                    float4 bj = S.wbox[j0 + t2];
                    float  aj = S.warea[j0 + t2];
                    float inter = fmaxf(fminf(bi.z, bj.z) - fmaxf(bi.x, bj.x), 0.0f)
                                * fmaxf(fminf(bi.w, bj.w) - fmaxf(bi.y, bj.y), 0.0f);
                    float un = ai + aj - inter;
                    float d  = fmaf(-NMS_TH, un, inter);
                    float mg = 2e-6f * (fabsf(inter) + fabsf(un));
                    bool sup = (un > 0.0f) ? (d > mg) : (d < -mg);
                    bool unc = !(fabsf(d) > mg) || (un == 0.0f);
                    if (sup) bits |= 1u << t2;
                    if (unc) uncb |= 1u << t2;
                }
                if (uncb) {
                    do {
                        int t2 = __ffs(uncb) - 1; uncb &= uncb - 1;
                        float4 bj = S.wbox[j0 + t2];
                        float  aj = S.warea[j0 + t2];
                        float inter = fmaxf(fminf(bi.z, bj.z) - fmaxf(bi.x, bj.x), 0.0f)
                                    * fmaxf(fminf(bi.w, bj.w) - fmaxf(bi.y, bj.y), 0.0f);
                        float un = ai + aj - inter;
                        if (__fdiv_rn(inter, un) > NMS_TH) bits |= 1u << t2;
                        else bits &= ~(1u << t2);
                    } while (uncb);
                }
                if (g == w) bits &= (0xFFFFFFFEu << lane);
                if (rv) S.wmask[w * MPITCH + i] = bits;
            }
        }
    }
    __syncthreads();

    // ---- Phase E: compact greedy sweep (warp 0) ----
    if (warp == 0 && nwf > 0) {
        unsigned acc = 0;
        for (int w = 0; w < ngw; ++w) {
            unsigned cur = __shfl_sync(0xFFFFFFFFu, acc, w);
            unsigned chunkkeep = 0;
            for (int sub = 0; sub < 4; ++sub) {
                const int ibase = w * 32 + sub * 8;
                if (ibase >= nwf) break;
                const int nv = min(8, nwf - ibase);
                const unsigned validm = (nv == 8) ? 0xFFu : ((1u << nv) - 1u);
                unsigned selfm[8], rowm[8], selfor = 0;
                #pragma unroll
                for (int t = 0; t < 8; ++t) {
                    bool vld = t < nv;
                    int i = ibase + t;
                    selfm[t] = vld ? S.wmask[w * MPITCH + i] : 0u;
                    rowm[t]  = (vld && lane >= w && lane < ngw)
                             ? S.wmask[lane * MPITCH + i] : 0u;
                    selfor |= selfm[t];
                }
                unsigned keepb;
                if (selfor == 0) {
                    keepb = validm & ~((cur >> (sub * 8)) & 0xFFu);
                    #pragma unroll
                    for (int t = 0; t < 8; ++t)
                        acc |= rowm[t] & (unsigned)(-(int)((keepb >> t) & 1u));
                } else {
                    keepb = 0;
                    #pragma unroll
                    for (int t = 0; t < 8; ++t) {
                        int kbit = sub * 8 + t;
                        if (((validm >> t) & 1u) && !((cur >> kbit) & 1u)) {
                            keepb |= 1u << t;
                            cur |= selfm[t];
                            acc |= rowm[t];
                        }
                    }
                }
                chunkkeep |= keepb << (sub * 8);
            }
            if (lane == 0) S.kwbits[w] = chunkkeep;
        }
    }
    __syncthreads();

    // ---- Phase F: flag scan + scatter output ----
    for (int cs = warp; cs < ngroups; cs += NWARPS) {
        int t = cs * 32 + lane;
        bool flag = false;
        if (t < M) {
            int ci = S.cidx[t];
            flag = (ci < 0) ? true : (((S.kwbits[ci >> 5] >> (ci & 31)) & 1u) != 0);
        }
        unsigned fb = __ballot_sync(0xFFFFFFFFu, flag);
        if (lane == 0) { S.flagb[cs] = fb; S.ctoff[cs] = __popc(fb); }
    }
    __syncthreads();
    if (tid == 0) {
        int run = 0;
        for (int cs = 0; cs < ngroups; ++cs) { int cc = S.ctoff[cs]; S.ctoff[cs] = run; run += cc; }
        S.ntot = run;
    }
    __syncthreads();
    const int n = min(S.ntot, TOPK);
    const int fp = S.fp;

    for (int cs = warp; cs < ngroups; cs += NWARPS) {
        int t = cs * 32 + lane;
        unsigned fb = S.flagb[cs];
        bool flag = ((fb >> lane) & 1u) && (t < M);
        int rank = S.ctoff[cs] + __popc(fb & lanem_lt);
        if (flag && rank < TOPK) {
            float sc = __uint_as_float((unsigned)(S.key[t] >> 32));
            float4 bb = S.box[t];
            float* o = outp + rank * 5;
            o[0] = sc; o[1] = bb.x; o[2] = bb.y; o[3] = bb.z; o[4] = bb.w;
        }
    }
    {
        float4 fb4 = __ldg((const float4*)(loc + ((size_t)b * NPRI + fp) * 4));
        for (int r = n + tid; r < TOPK; r += NTHREADS) {
            float* o = outp + r * 5;
            o[0] = 0.0f; o[1] = fb4.x; o[2] = fb4.y; o[3] = fb4.z; o[4] = fb4.w;
        }
    }
}

extern "C" void kernel_launch(void* const* d_in, const int* in_sizes, int n_in,
                              void* d_out, int out_size)
{
    const float* loc  = (const float*)d_in[0];   // [8, 8732, 4]
    const float* conf = (const float*)d_in[1];   // [8, 8732, 21]
    float* out = (float*)d_out;                  // [8, 21, 200, 5]

    static int configured = 0;
    if (!configured) {
        cudaFuncSetAttribute(detect_kernel,
                             cudaFuncAttributeMaxDynamicSharedMemorySize,
                             (int)sizeof(Smem));
        configured = 1;
    }
    k0_transpose<<<NBATCH * 273, 672>>>(conf);
    detect_kernel<<<NLANES, NTHREADS, sizeof(Smem)>>>(loc, out);
}